// round 5
// baseline (speedup 1.0000x reference)
#include <cuda_runtime.h>
#include <math.h>

// Problem constants
#define HW    4096          // 64*64 latent positions
#define CC    320           // hidden channels
#define CX    768           // encoder channels
#define LKV   77            // encoder seq len
#define DH    40            // head dim
#define NHEAD 8
#define NBATCH 10           // attention batches (ehs[:-1])
#define NINST 8             // boxes
#define LATENT 64

typedef unsigned long long u64;

// ---------------- packed f32x2 helpers (Blackwell FFMA2 path) ----------------
__device__ __forceinline__ u64 ffma2(u64 a, u64 b, u64 c) {
    u64 d;
    asm("fma.rn.f32x2 %0, %1, %2, %3;" : "=l"(d) : "l"(a), "l"(b), "l"(c));
    return d;
}
__device__ __forceinline__ u64 fmul2(u64 a, u64 b) {
    u64 d;
    asm("mul.rn.f32x2 %0, %1, %2;" : "=l"(d) : "l"(a), "l"(b));
    return d;
}
__device__ __forceinline__ u64 pack2(float x, float y) {
    u64 r;
    asm("mov.b64 %0, {%1, %2};" : "=l"(r) : "f"(x), "f"(y));
    return r;
}
__device__ __forceinline__ void unpack2(u64 v, float& lo, float& hi) {
    asm("mov.b64 {%0, %1}, %2;" : "=f"(lo), "=f"(hi) : "l"(v));
}

// ---------------- scratch (device globals; allocation is banned) -------------
__device__ float g_Q[2 * HW * CC];        // 2 distinct hidden states projected
__device__ float g_K[NBATCH * LKV * CC];
__device__ float g_V[NBATCH * LKV * CC];
__device__ float g_attn[9 * HW * CC];     // attention out for batches 1..9
__device__ float g_final[2 * HW * CC];    // rows 0..4095: attn batch0; 4096..: weighted
__device__ float g_pw[9 * HW];            // phase weights
__device__ float g_bscale[HW];            // s/(s+eps) for bias term on fused rows

// ---------------- tiled SGEMM with FFMA2: C = A(MxK) @ B(KxN) ----------------
// BM=BN=64, BK=16, 256 threads, 4x4 microtile (as 4x2 f32x2 pairs).
// A tile stored DUPLICATED in smem so the a-operand dup is a free LDS.64.
__global__ __launch_bounds__(256) void sgemm_kernel(
    const float* __restrict__ A, const float* __restrict__ B, float* __restrict__ Cm,
    int M, int N, int K,
    const float* __restrict__ bias, const float* __restrict__ bscale, int mode)
{
    __shared__ u64  As2[16][64];          // As2[k][r] = (A[r][k], A[r][k])
    __shared__ float Bs[16][64];

    int tid = threadIdx.x;
    int row0 = blockIdx.y * 64;
    int col0 = blockIdx.x * 64;
    int ty = tid / 16, tx = tid % 16;
    int ty4 = ty * 4;

    int arow = tid >> 2;            // 0..63
    int acol = (tid & 3) * 4;       // 0,4,8,12
    int brow = tid >> 4;            // 0..15
    int bcol = (tid & 15) * 4;      // 0..60

    u64 acc[4][2];
#pragma unroll
    for (int i = 0; i < 4; i++) { acc[i][0] = 0ull; acc[i][1] = 0ull; }

    for (int k0 = 0; k0 < K; k0 += 16) {
        float4 a4 = make_float4(0.f, 0.f, 0.f, 0.f);
        if (row0 + arow < M)
            a4 = *reinterpret_cast<const float4*>(&A[(size_t)(row0 + arow) * K + k0 + acol]);
        As2[acol + 0][arow] = pack2(a4.x, a4.x);
        As2[acol + 1][arow] = pack2(a4.y, a4.y);
        As2[acol + 2][arow] = pack2(a4.z, a4.z);
        As2[acol + 3][arow] = pack2(a4.w, a4.w);

        float4 b4 = *reinterpret_cast<const float4*>(&B[(size_t)(k0 + brow) * N + col0 + bcol]);
        *reinterpret_cast<float4*>(&Bs[brow][bcol]) = b4;
        __syncthreads();

#pragma unroll
        for (int k = 0; k < 16; ++k) {
            ulonglong2 rb = *reinterpret_cast<const ulonglong2*>(&Bs[k][tx * 4]);
            u64 ra0 = As2[k][ty4 + 0];
            u64 ra1 = As2[k][ty4 + 1];
            u64 ra2 = As2[k][ty4 + 2];
            u64 ra3 = As2[k][ty4 + 3];
            acc[0][0] = ffma2(ra0, rb.x, acc[0][0]);
            acc[0][1] = ffma2(ra0, rb.y, acc[0][1]);
            acc[1][0] = ffma2(ra1, rb.x, acc[1][0]);
            acc[1][1] = ffma2(ra1, rb.y, acc[1][1]);
            acc[2][0] = ffma2(ra2, rb.x, acc[2][0]);
            acc[2][1] = ffma2(ra2, rb.y, acc[2][1]);
            acc[3][0] = ffma2(ra3, rb.x, acc[3][0]);
            acc[3][1] = ffma2(ra3, rb.y, acc[3][1]);
        }
        __syncthreads();
    }

#pragma unroll
    for (int i = 0; i < 4; i++) {
        int row = row0 + ty4 + i;
        if (row >= M) continue;
        float v[4];
        unpack2(acc[i][0], v[0], v[1]);
        unpack2(acc[i][1], v[2], v[3]);
#pragma unroll
        for (int j = 0; j < 4; j++) {
            int col = col0 + tx * 4 + j;
            float val = v[j];
            if (mode == 1) {
                float bs = (row < HW) ? 1.0f : bscale[row - HW];
                val += bias[col] * bs;
            }
            Cm[(size_t)row * N + col] = val;
        }
    }
}

// ---------------- separable antialiased triangle resize weights --------------
__device__ __forceinline__ float axis_weight(int o, float lo, float hi)
{
    float c = 8.0f * o + 3.5f;
    int j0 = 8 * o - 4;
    int j1 = 8 * o + 11;
    if (j0 < 0) j0 = 0;
    if (j1 > 511) j1 = 511;
    float wsum = 0.0f, win = 0.0f;
    for (int j = j0; j <= j1; ++j) {
        float w = 1.0f - fabsf((float)j - c) * 0.125f;
        wsum += w;
        float jf = (float)j;
        if (jf >= lo && jf < hi) win += w;
    }
    return win / wsum;
}

__global__ __launch_bounds__(128) void mask_kernel(
    const float* __restrict__ bboxes, float* __restrict__ pw)
{
    int idx = blockIdx.x * 128 + threadIdx.x;   // 0 .. 9*HW-1
    if (idx >= 9 * HW) return;
    int n = idx / HW;
    int pos = idx - n * HW;
    if (n == 0) { pw[pos] = 0.1f; return; }
    int y = pos >> 6;
    int x = pos & 63;
    const float* bb = bboxes + (n - 1) * 4;
    float wmin = floorf(512.0f * bb[0]);
    float hmin = floorf(512.0f * bb[1]);
    float wmax = floorf(512.0f * bb[2]);
    float hmax = floorf(512.0f * bb[3]);
    float fy = axis_weight(y, hmin, hmax);
    float fx = axis_weight(x, wmin, wmax);
    pw[idx] = fy * fx * 10.0f;
}

// ---------------- attention with FFMA2: one block per (b, h, 128-row tile) ---
__global__ __launch_bounds__(128) void attn_kernel(
    const float* __restrict__ Q, const float* __restrict__ K, const float* __restrict__ V,
    float* __restrict__ attn_out, float* __restrict__ final_in)
{
    __shared__ float Ks[LKV][DH];
    __shared__ float Vs[LKV][DH];
    __shared__ float Qs[128][DH];

    int qt = blockIdx.x;   // 0..31
    int h  = blockIdx.y;   // 0..7
    int b  = blockIdx.z;   // 0..9
    int tid = threadIdx.x; // 0..127

    const float scale = 0.15811388300841897f;  // 1/sqrt(40)

    const float* Kb = K + (size_t)b * LKV * CC + h * DH;
    const float* Vb = V + (size_t)b * LKV * CC + h * DH;
    for (int idx = tid; idx < LKV * DH; idx += 128) {
        int r = idx / DH, c = idx % DH;
        Ks[r][c] = Kb[(size_t)r * CC + c];
        Vs[r][c] = Vb[(size_t)r * CC + c];
    }
    int qb = (b == 0) ? 0 : 1;
    int q0 = qt * 128;
    const float* Qb = Q + ((size_t)qb * HW + q0) * CC + h * DH;
    for (int idx = tid; idx < 128 * DH; idx += 128) {
        int r = idx / DH, c = idx % DH;
        Qs[r][c] = Qb[(size_t)r * CC + c] * scale;   // fold softmax scale here
    }
    __syncthreads();

    // q and accumulator as packed f32x2 pairs along head dim
    u64 qp[DH / 2], acc[DH / 2];
    {
        const u64* qrow = reinterpret_cast<const u64*>(&Qs[tid][0]);
#pragma unroll
        for (int d2 = 0; d2 < DH / 2; ++d2) { qp[d2] = qrow[d2]; acc[d2] = 0ull; }
    }

    float l = 0.0f;
    for (int j = 0; j < LKV; ++j) {
        const ulonglong2* k4 = reinterpret_cast<const ulonglong2*>(&Ks[j][0]);
        u64 sdot = 0ull;
#pragma unroll
        for (int d4 = 0; d4 < DH / 4; ++d4) {
            ulonglong2 kk = k4[d4];
            sdot = ffma2(qp[d4 * 2 + 0], kk.x, sdot);
            sdot = ffma2(qp[d4 * 2 + 1], kk.y, sdot);
        }
        float slo, shi;
        unpack2(sdot, slo, shi);
        float p = __expf(slo + shi);   // logits ~O(1): safe without max-sub
        l += p;
        u64 pp = pack2(p, p);
        const ulonglong2* v4 = reinterpret_cast<const ulonglong2*>(&Vs[j][0]);
#pragma unroll
        for (int d4 = 0; d4 < DH / 4; ++d4) {
            ulonglong2 vv = v4[d4];
            acc[d4 * 2 + 0] = ffma2(pp, vv.x, acc[d4 * 2 + 0]);
            acc[d4 * 2 + 1] = ffma2(pp, vv.y, acc[d4 * 2 + 1]);
        }
    }

    float inv = 1.0f / l;
    u64 invp = pack2(inv, inv);
    float* dst = (b == 0)
        ? (final_in + ((size_t)(q0 + tid)) * CC + h * DH)
        : (attn_out + ((size_t)(b - 1) * HW + q0 + tid) * CC + h * DH);
    ulonglong2* dst2 = reinterpret_cast<ulonglong2*>(dst);
#pragma unroll
    for (int d4 = 0; d4 < DH / 4; ++d4) {
        ulonglong2 o;
        o.x = fmul2(acc[d4 * 2 + 0], invp);
        o.y = fmul2(acc[d4 * 2 + 1], invp);
        dst2[d4] = o;
    }
}

// ---------------- weighted fusion of the 9 conditional attention outputs -----
__global__ __launch_bounds__(CC) void reduce_kernel(
    const float* __restrict__ attn, const float* __restrict__ pw,
    float* __restrict__ final_in, float* __restrict__ bscale)
{
    int pos = blockIdx.x;   // 0..4095
    int c = threadIdx.x;    // 0..319
    __shared__ float w[9];
    __shared__ float sinv;
    if (c < 9) w[c] = pw[(size_t)c * HW + pos];
    __syncthreads();
    if (c == 0) {
        float s = 0.0f;
        for (int i = 0; i < 9; i++) s += w[i];
        float iv = 1.0f / (s + 1e-6f);
        sinv = iv;
        bscale[pos] = s * iv;
    }
    __syncthreads();
    float accv = 0.0f;
#pragma unroll
    for (int i = 0; i < 9; i++)
        accv += w[i] * attn[((size_t)i * HW + pos) * CC + c];
    final_in[((size_t)(HW + pos)) * CC + c] = accv * sinv;
}

// ---------------- launch ------------------------------------------------------
extern "C" void kernel_launch(void* const* d_in, const int* in_sizes, int n_in,
                              void* d_out, int out_size)
{
    const float* hidden = (const float*)d_in[0];   // (2, 4096, 320)
    const float* ehs    = (const float*)d_in[1];   // (11, 77, 768)
    const float* bbox   = (const float*)d_in[2];   // (1, 8, 4)
    const float* Wq     = (const float*)d_in[3];
    const float* Wk     = (const float*)d_in[4];
    const float* Wv     = (const float*)d_in[5];
    const float* Wo     = (const float*)d_in[6];
    const float* bo     = (const float*)d_in[7];
    float* out = (float*)d_out;

    float *Qp, *Kp, *Vp, *Ap, *Fp, *Pp, *Bp;
    cudaGetSymbolAddress((void**)&Qp, g_Q);
    cudaGetSymbolAddress((void**)&Kp, g_K);
    cudaGetSymbolAddress((void**)&Vp, g_V);
    cudaGetSymbolAddress((void**)&Ap, g_attn);
    cudaGetSymbolAddress((void**)&Fp, g_final);
    cudaGetSymbolAddress((void**)&Pp, g_pw);
    cudaGetSymbolAddress((void**)&Bp, g_bscale);

    // Q projection on the 2 DISTINCT hidden states only (batches 1..9 share q)
    sgemm_kernel<<<dim3(CC / 64, (2 * HW) / 64), 256>>>(
        hidden, Wq, Qp, 2 * HW, CC, CC, nullptr, nullptr, 0);

    // K / V projections on ehs[:-1] = first 770 rows
    sgemm_kernel<<<dim3(CC / 64, (NBATCH * LKV + 63) / 64), 256>>>(
        ehs, Wk, Kp, NBATCH * LKV, CC, CX, nullptr, nullptr, 0);
    sgemm_kernel<<<dim3(CC / 64, (NBATCH * LKV + 63) / 64), 256>>>(
        ehs, Wv, Vp, NBATCH * LKV, CC, CX, nullptr, nullptr, 0);

    // phase weights from bboxes (separable antialiased resize)
    mask_kernel<<<(9 * HW + 127) / 128, 128>>>(bbox, Pp);

    // attention for 10 batches x 8 heads
    attn_kernel<<<dim3(HW / 128, NHEAD, NBATCH), 128>>>(Qp, Kp, Vp, Ap, Fp);

    // weighted fusion of conditional batches (Wo deferred; linearity)
    reduce_kernel<<<HW, CC>>>(Ap, Pp, Fp, Bp);

    // final projection of [attn_uncond ; fused] + bias
    sgemm_kernel<<<dim3(CC / 64, (2 * HW) / 64), 256>>>(
        Fp, Wo, out, 2 * HW, CC, CC, bo, Bp, 1);
}

// round 7
// speedup vs baseline: 1.2639x; 1.2639x over previous
#include <cuda_runtime.h>
#include <math.h>
#include <cstdint>

// Problem constants
#define HW    4096
#define CC    320
#define CX    768
#define LKV   77
#define DH    40
#define NHEAD 8
#define NBATCH 10
#define NINST 8

// ======================= scratch (allocation is banned) ======================
__device__ float g_Q[2 * HW * CC];
__device__ float g_K[NBATCH * LKV * CC];
__device__ float g_V[NBATCH * LKV * CC];
__device__ float g_attn[9 * HW * CC];
__device__ float g_final[2 * HW * CC];
__device__ float g_pw[9 * HW];
__device__ float g_bscale[HW];

// ======================= tf32 helpers ========================================
__device__ __forceinline__ float tf32r(float v) {
    uint32_t t;
    asm("cvt.rna.tf32.f32 %0, %1;" : "=r"(t) : "f"(v));
    return __uint_as_float(t);
}
__device__ __forceinline__ void mma_tf32(float c[4], const uint32_t a[4], const uint32_t b[2]) {
    asm volatile(
        "mma.sync.aligned.m16n8k8.row.col.f32.tf32.tf32.f32 "
        "{%0,%1,%2,%3}, {%4,%5,%6,%7}, {%8,%9}, {%0,%1,%2,%3};"
        : "+f"(c[0]), "+f"(c[1]), "+f"(c[2]), "+f"(c[3])
        : "r"(a[0]), "r"(a[1]), "r"(a[2]), "r"(a[3]), "r"(b[0]), "r"(b[1]));
}

// ======================= tf32 tensor-core GEMM ===============================
// C[M x 320] = A[M x K] @ W[K x 320]  (W used in native row-major layout).
// Block tile 128x64, 8 warps (4x2), warp tile 32x32, K chunks of 32.
#define AST 36   // As row stride (floats): (4g+tg) banks all distinct
#define BST 72   // Bs row stride (floats): same property

__global__ __launch_bounds__(256) void gemm_tf32(
    const float* __restrict__ A, const float* __restrict__ W, float* __restrict__ Cm,
    int M, int K,
    const float* __restrict__ bias, const float* __restrict__ bscale, int mode)
{
    __shared__ float As[128 * AST];
    __shared__ float Bs[32 * BST];

    int tid = threadIdx.x;
    int wid = tid >> 5, lane = tid & 31;
    int g = lane >> 2, tg = lane & 3;
    int wm = wid & 3, wn = wid >> 2;
    int m0 = blockIdx.y * 128, n0 = blockIdx.x * 64;

    float c[2][4][4];
#pragma unroll
    for (int i = 0; i < 2; ++i)
#pragma unroll
        for (int j = 0; j < 4; ++j)
#pragma unroll
            for (int f = 0; f < 4; ++f) c[i][j][f] = 0.0f;

    for (int k0 = 0; k0 < K; k0 += 32) {
        // A tile: 128 rows x 32 k, row-major in SMEM (tf32-rounded)
#pragma unroll
        for (int i = 0; i < 4; ++i) {
            int idx = i * 256 + tid;          // 0..1023
            int r = idx >> 3, c4 = idx & 7;
            float4 a4 = make_float4(0.f, 0.f, 0.f, 0.f);
            if (m0 + r < M)
                a4 = *reinterpret_cast<const float4*>(A + (size_t)(m0 + r) * K + k0 + c4 * 4);
            float4 t = make_float4(tf32r(a4.x), tf32r(a4.y), tf32r(a4.z), tf32r(a4.w));
            *reinterpret_cast<float4*>(&As[r * AST + c4 * 4]) = t;
        }
        // B tile: 32 k-rows x 64 n, native W layout (tf32-rounded)
#pragma unroll
        for (int i = 0; i < 2; ++i) {
            int idx = i * 256 + tid;          // 0..511
            int kr = idx >> 4, c4 = idx & 15;
            float4 b4 = *reinterpret_cast<const float4*>(W + (size_t)(k0 + kr) * CC + n0 + c4 * 4);
            float4 t = make_float4(tf32r(b4.x), tf32r(b4.y), tf32r(b4.z), tf32r(b4.w));
            *reinterpret_cast<float4*>(&Bs[kr * BST + c4 * 4]) = t;
        }
        __syncthreads();

#pragma unroll
        for (int k8 = 0; k8 < 4; ++k8) {
            int kb = k8 * 8;
            uint32_t a[2][4], b[4][2];
#pragma unroll
            for (int i = 0; i < 2; ++i) {
                int mb = (wm * 32 + i * 16 + g) * AST + kb + tg;
                a[i][0] = __float_as_uint(As[mb]);
                a[i][1] = __float_as_uint(As[mb + 8 * AST]);
                a[i][2] = __float_as_uint(As[mb + 4]);
                a[i][3] = __float_as_uint(As[mb + 8 * AST + 4]);
            }
#pragma unroll
            for (int j = 0; j < 4; ++j) {
                int nb = wn * 32 + j * 8 + g;
                b[j][0] = __float_as_uint(Bs[(kb + tg) * BST + nb]);
                b[j][1] = __float_as_uint(Bs[(kb + tg + 4) * BST + nb]);
            }
#pragma unroll
            for (int i = 0; i < 2; ++i)
#pragma unroll
                for (int j = 0; j < 4; ++j)
                    mma_tf32(c[i][j], a[i], b[j]);
        }
        __syncthreads();
    }

    // Epilogue: warp writes its 32x32 tile (float2 per fragment row)
#pragma unroll
    for (int i = 0; i < 2; ++i) {
        int r0 = m0 + wm * 32 + i * 16 + g;
#pragma unroll
        for (int j = 0; j < 4; ++j) {
            int col = n0 + wn * 32 + j * 8 + 2 * tg;
#pragma unroll
            for (int h = 0; h < 2; ++h) {
                int row = r0 + h * 8;
                if (row >= M) continue;
                float v0 = c[i][j][h * 2 + 0];
                float v1 = c[i][j][h * 2 + 1];
                if (mode == 1) {
                    float bs = (row < HW) ? 1.0f : bscale[row - HW];
                    v0 += bias[col] * bs;
                    v1 += bias[col + 1] * bs;
                }
                *reinterpret_cast<float2*>(Cm + (size_t)row * CC + col) = make_float2(v0, v1);
            }
        }
    }
}

// ======================= mask (separable antialiased resize) =================
__device__ __forceinline__ float axis_weight(int o, float lo, float hi)
{
    float c = 8.0f * o + 3.5f;
    int j0 = 8 * o - 4; if (j0 < 0) j0 = 0;
    int j1 = 8 * o + 11; if (j1 > 511) j1 = 511;
    float wsum = 0.0f, win = 0.0f;
    for (int j = j0; j <= j1; ++j) {
        float w = 1.0f - fabsf((float)j - c) * 0.125f;
        wsum += w;
        float jf = (float)j;
        if (jf >= lo && jf < hi) win += w;
    }
    return win / wsum;
}

__global__ __launch_bounds__(128) void mask_kernel(
    const float* __restrict__ bboxes, float* __restrict__ pw)
{
    int idx = blockIdx.x * 128 + threadIdx.x;
    if (idx >= 9 * HW) return;
    int n = idx / HW;
    int pos = idx - n * HW;
    if (n == 0) { pw[pos] = 0.1f; return; }
    int y = pos >> 6, x = pos & 63;
    const float* bb = bboxes + (n - 1) * 4;
    float wmin = floorf(512.0f * bb[0]);
    float hmin = floorf(512.0f * bb[1]);
    float wmax = floorf(512.0f * bb[2]);
    float hmax = floorf(512.0f * bb[3]);
    pw[idx] = axis_weight(y, hmin, hmax) * axis_weight(x, wmin, wmax) * 10.0f;
}

// ======================= attention (scalar, R3-proven) =======================
__global__ __launch_bounds__(128) void attn_kernel(
    const float* __restrict__ Q, const float* __restrict__ K, const float* __restrict__ V,
    float* __restrict__ attn_out, float* __restrict__ final_in)
{
    __shared__ float Ks[LKV][DH];
    __shared__ float Vs[LKV][DH];
    __shared__ float Qs[128][DH];

    int qt = blockIdx.x, h = blockIdx.y, b = blockIdx.z;
    int tid = threadIdx.x;
    const float scale = 0.15811388300841897f;  // 1/sqrt(40)

    const float* Kb = K + (size_t)b * LKV * CC + h * DH;
    const float* Vb = V + (size_t)b * LKV * CC + h * DH;
    for (int idx = tid; idx < LKV * DH; idx += 128) {
        int r = idx / DH, c = idx % DH;
        Ks[r][c] = Kb[(size_t)r * CC + c];
        Vs[r][c] = Vb[(size_t)r * CC + c];
    }
    int qb = (b == 0) ? 0 : 1;
    int q0 = qt * 128;
    const float* Qb = Q + ((size_t)qb * HW + q0) * CC + h * DH;
    for (int idx = tid; idx < 128 * DH; idx += 128) {
        int r = idx / DH, c = idx % DH;
        Qs[r][c] = Qb[(size_t)r * CC + c] * scale;
    }
    __syncthreads();

    float q[DH], acc[DH];
#pragma unroll
    for (int d = 0; d < DH; d++) { q[d] = Qs[tid][d]; acc[d] = 0.0f; }

    float l = 0.0f;
    for (int j = 0; j < LKV; ++j) {
        const float4* k4 = reinterpret_cast<const float4*>(&Ks[j][0]);
        float s = 0.0f;
#pragma unroll
        for (int d4 = 0; d4 < DH / 4; ++d4) {
            float4 kk = k4[d4];
            s += q[d4 * 4 + 0] * kk.x;
            s += q[d4 * 4 + 1] * kk.y;
            s += q[d4 * 4 + 2] * kk.z;
            s += q[d4 * 4 + 3] * kk.w;
        }
        float p = __expf(s);
        l += p;
        const float4* v4 = reinterpret_cast<const float4*>(&Vs[j][0]);
#pragma unroll
        for (int d4 = 0; d4 < DH / 4; ++d4) {
            float4 vv = v4[d4];
            acc[d4 * 4 + 0] += p * vv.x;
            acc[d4 * 4 + 1] += p * vv.y;
            acc[d4 * 4 + 2] += p * vv.z;
            acc[d4 * 4 + 3] += p * vv.w;
        }
    }

    float inv = 1.0f / l;
    float* dst = (b == 0)
        ? (final_in + ((size_t)(q0 + tid)) * CC + h * DH)
        : (attn_out + ((size_t)(b - 1) * HW + q0 + tid) * CC + h * DH);
#pragma unroll
    for (int d4 = 0; d4 < DH / 4; ++d4) {
        float4 o;
        o.x = acc[d4 * 4 + 0] * inv;
        o.y = acc[d4 * 4 + 1] * inv;
        o.z = acc[d4 * 4 + 2] * inv;
        o.w = acc[d4 * 4 + 3] * inv;
        *reinterpret_cast<float4*>(dst + d4 * 4) = o;
    }
}

// ======================= weighted fusion =====================================
__global__ __launch_bounds__(CC) void reduce_kernel(
    const float* __restrict__ attn, const float* __restrict__ pw,
    float* __restrict__ final_in, float* __restrict__ bscale)
{
    int pos = blockIdx.x;
    int c = threadIdx.x;
    __shared__ float w[9];
    __shared__ float sinv;
    if (c < 9) w[c] = pw[(size_t)c * HW + pos];
    __syncthreads();
    if (c == 0) {
        float s = 0.0f;
        for (int i = 0; i < 9; i++) s += w[i];
        float iv = 1.0f / (s + 1e-6f);
        sinv = iv;
        bscale[pos] = s * iv;
    }
    __syncthreads();
    float accv = 0.0f;
#pragma unroll
    for (int i = 0; i < 9; i++)
        accv += w[i] * attn[((size_t)i * HW + pos) * CC + c];
    final_in[((size_t)(HW + pos)) * CC + c] = accv * sinv;
}

// ======================= launch ==============================================
extern "C" void kernel_launch(void* const* d_in, const int* in_sizes, int n_in,
                              void* d_out, int out_size)
{
    const float* hidden = (const float*)d_in[0];   // (2, 4096, 320)
    const float* ehs    = (const float*)d_in[1];   // (11, 77, 768)
    const float* bbox   = (const float*)d_in[2];   // (1, 8, 4)
    const float* Wq     = (const float*)d_in[3];
    const float* Wk     = (const float*)d_in[4];
    const float* Wv     = (const float*)d_in[5];
    const float* Wo     = (const float*)d_in[6];
    const float* bo     = (const float*)d_in[7];
    float* out = (float*)d_out;

    float *Qp, *Kp, *Vp, *Ap, *Fp, *Pp, *Bp;
    cudaGetSymbolAddress((void**)&Qp, g_Q);
    cudaGetSymbolAddress((void**)&Kp, g_K);
    cudaGetSymbolAddress((void**)&Vp, g_V);
    cudaGetSymbolAddress((void**)&Ap, g_attn);
    cudaGetSymbolAddress((void**)&Fp, g_final);
    cudaGetSymbolAddress((void**)&Pp, g_pw);
    cudaGetSymbolAddress((void**)&Bp, g_bscale);

    // Q projection (tensor cores, tf32): 2 distinct hidden states only
    gemm_tf32<<<dim3(CC / 64, (2 * HW + 127) / 128), 256>>>(
        hidden, Wq, Qp, 2 * HW, CC, nullptr, nullptr, 0);

    // K / V projections on ehs[:-1] = first 770 rows
    gemm_tf32<<<dim3(CC / 64, (NBATCH * LKV + 127) / 128), 256>>>(
        ehs, Wk, Kp, NBATCH * LKV, CX, nullptr, nullptr, 0);
    gemm_tf32<<<dim3(CC / 64, (NBATCH * LKV + 127) / 128), 256>>>(
        ehs, Wv, Vp, NBATCH * LKV, CX, nullptr, nullptr, 0);

    // phase weights
    mask_kernel<<<(9 * HW + 127) / 128, 128>>>(bbox, Pp);

    // attention + weighted fusion (Wo deferred through linearity)
    attn_kernel<<<dim3(HW / 128, NHEAD, NBATCH), 128>>>(Qp, Kp, Vp, Ap, Fp);
    reduce_kernel<<<HW, CC>>>(Ap, Pp, Fp, Bp);

    // output projection (tensor cores) + bias epilogue
    gemm_tf32<<<dim3(CC / 64, (2 * HW + 127) / 128), 256>>>(
        Fp, Wo, out, 2 * HW, CC, bo, Bp, 1);
}

// round 9
// speedup vs baseline: 2.2309x; 1.7650x over previous
#include <cuda_runtime.h>
#include <math.h>
#include <cstdint>

// Problem constants
#define HW    4096
#define CC    320
#define CX    768
#define LKV   77
#define DH    40
#define NHEAD 8
#define NBATCH 10
#define NINST 8

// ======================= scratch (allocation is banned) ======================
__device__ float g_Q[2 * HW * CC];
__device__ float g_K[NBATCH * LKV * CC];
__device__ float g_V[NBATCH * LKV * CC];
__device__ float g_attn[9 * HW * CC];
__device__ float g_final[2 * HW * CC];
__device__ float g_pw[9 * HW];
__device__ float g_bscale[HW];

// ======================= tf32 helpers ========================================
__device__ __forceinline__ float tf32r(float v) {
    uint32_t t;
    asm("cvt.rna.tf32.f32 %0, %1;" : "=r"(t) : "f"(v));
    return __uint_as_float(t);
}
__device__ __forceinline__ void mma_tf32(float c[4], const uint32_t a[4], const uint32_t b[2]) {
    asm volatile(
        "mma.sync.aligned.m16n8k8.row.col.f32.tf32.tf32.f32 "
        "{%0,%1,%2,%3}, {%4,%5,%6,%7}, {%8,%9}, {%0,%1,%2,%3};"
        : "+f"(c[0]), "+f"(c[1]), "+f"(c[2]), "+f"(c[3])
        : "r"(a[0]), "r"(a[1]), "r"(a[2]), "r"(a[3]), "r"(b[0]), "r"(b[1]));
}

// ======================= tf32 tensor-core GEMM (R7-proven) ===================
#define AST 36
#define BST 72

__global__ __launch_bounds__(256) void gemm_tf32(
    const float* __restrict__ A, const float* __restrict__ W, float* __restrict__ Cm,
    int M, int K,
    const float* __restrict__ bias, const float* __restrict__ bscale, int mode)
{
    __shared__ float As[128 * AST];
    __shared__ float Bs[32 * BST];

    int tid = threadIdx.x;
    int wid = tid >> 5, lane = tid & 31;
    int g = lane >> 2, tg = lane & 3;
    int wm = wid & 3, wn = wid >> 2;
    int m0 = blockIdx.y * 128, n0 = blockIdx.x * 64;

    float c[2][4][4];
#pragma unroll
    for (int i = 0; i < 2; ++i)
#pragma unroll
        for (int j = 0; j < 4; ++j)
#pragma unroll
            for (int f = 0; f < 4; ++f) c[i][j][f] = 0.0f;

    for (int k0 = 0; k0 < K; k0 += 32) {
#pragma unroll
        for (int i = 0; i < 4; ++i) {
            int idx = i * 256 + tid;
            int r = idx >> 3, c4 = idx & 7;
            float4 a4 = make_float4(0.f, 0.f, 0.f, 0.f);
            if (m0 + r < M)
                a4 = *reinterpret_cast<const float4*>(A + (size_t)(m0 + r) * K + k0 + c4 * 4);
            float4 t = make_float4(tf32r(a4.x), tf32r(a4.y), tf32r(a4.z), tf32r(a4.w));
            *reinterpret_cast<float4*>(&As[r * AST + c4 * 4]) = t;
        }
#pragma unroll
        for (int i = 0; i < 2; ++i) {
            int idx = i * 256 + tid;
            int kr = idx >> 4, c4 = idx & 15;
            float4 b4 = *reinterpret_cast<const float4*>(W + (size_t)(k0 + kr) * CC + n0 + c4 * 4);
            float4 t = make_float4(tf32r(b4.x), tf32r(b4.y), tf32r(b4.z), tf32r(b4.w));
            *reinterpret_cast<float4*>(&Bs[kr * BST + c4 * 4]) = t;
        }
        __syncthreads();

#pragma unroll
        for (int k8 = 0; k8 < 4; ++k8) {
            int kb = k8 * 8;
            uint32_t a[2][4], b[4][2];
#pragma unroll
            for (int i = 0; i < 2; ++i) {
                int mb = (wm * 32 + i * 16 + g) * AST + kb + tg;
                a[i][0] = __float_as_uint(As[mb]);
                a[i][1] = __float_as_uint(As[mb + 8 * AST]);
                a[i][2] = __float_as_uint(As[mb + 4]);
                a[i][3] = __float_as_uint(As[mb + 8 * AST + 4]);
            }
#pragma unroll
            for (int j = 0; j < 4; ++j) {
                int nb = wn * 32 + j * 8 + g;
                b[j][0] = __float_as_uint(Bs[(kb + tg) * BST + nb]);
                b[j][1] = __float_as_uint(Bs[(kb + tg + 4) * BST + nb]);
            }
#pragma unroll
            for (int i = 0; i < 2; ++i)
#pragma unroll
                for (int j = 0; j < 4; ++j)
                    mma_tf32(c[i][j], a[i], b[j]);
        }
        __syncthreads();
    }

#pragma unroll
    for (int i = 0; i < 2; ++i) {
        int r0 = m0 + wm * 32 + i * 16 + g;
#pragma unroll
        for (int j = 0; j < 4; ++j) {
            int col = n0 + wn * 32 + j * 8 + 2 * tg;
#pragma unroll
            for (int h = 0; h < 2; ++h) {
                int row = r0 + h * 8;
                if (row >= M) continue;
                float v0 = c[i][j][h * 2 + 0];
                float v1 = c[i][j][h * 2 + 1];
                if (mode == 1) {
                    float bs = (row < HW) ? 1.0f : bscale[row - HW];
                    v0 += bias[col] * bs;
                    v1 += bias[col + 1] * bs;
                }
                *reinterpret_cast<float2*>(Cm + (size_t)row * CC + col) = make_float2(v0, v1);
            }
        }
    }
}

// ======================= mask (separable antialiased resize) =================
__device__ __forceinline__ float axis_weight(int o, float lo, float hi)
{
    float c = 8.0f * o + 3.5f;
    int j0 = 8 * o - 4; if (j0 < 0) j0 = 0;
    int j1 = 8 * o + 11; if (j1 > 511) j1 = 511;
    float wsum = 0.0f, win = 0.0f;
    for (int j = j0; j <= j1; ++j) {
        float w = 1.0f - fabsf((float)j - c) * 0.125f;
        wsum += w;
        float jf = (float)j;
        if (jf >= lo && jf < hi) win += w;
    }
    return win / wsum;
}

__global__ __launch_bounds__(128) void mask_kernel(
    const float* __restrict__ bboxes, float* __restrict__ pw)
{
    int idx = blockIdx.x * 128 + threadIdx.x;
    if (idx >= 9 * HW) return;
    int n = idx / HW;
    int pos = idx - n * HW;
    if (n == 0) { pw[pos] = 0.1f; return; }
    int y = pos >> 6, x = pos & 63;
    const float* bb = bboxes + (n - 1) * 4;
    float wmin = floorf(512.0f * bb[0]);
    float hmin = floorf(512.0f * bb[1]);
    float wmax = floorf(512.0f * bb[2]);
    float hmax = floorf(512.0f * bb[3]);
    pw[idx] = axis_weight(y, hmin, hmax) * axis_weight(x, wmin, wmax) * 10.0f;
}

// ======================= tensor-core attention with sparsity =================
// One block: (128 q-rows, head h, batch b). 8 warps, each owns 16 q-rows.
// S/Q share one buffer: S[128][84]. Ks[80][44], Vs[80][40] (rows 77..79 zero).
#define QST 84
#define KST 44
#define VST 40
#define ATTN_SMEM ((128 * QST + 80 * KST + 80 * VST) * 4)

__global__ __launch_bounds__(256) void attn_kernel(
    const float* __restrict__ Q, const float* __restrict__ K, const float* __restrict__ V,
    const float* __restrict__ bboxes,
    float* __restrict__ attn_out, float* __restrict__ final_in)
{
    extern __shared__ float sm[];
    float* S  = sm;                       // Q then P
    float* Ks = sm + 128 * QST;
    float* Vs = Ks + 80 * KST;

    int qt = blockIdx.x, h = blockIdx.y, b = blockIdx.z;
    int tid = threadIdx.x;
    int wid = tid >> 5, lane = tid & 31;
    int g = lane >> 2, tg = lane & 3;
    int q0 = qt * 128;
    int r0 = q0 >> 6;                     // block covers image rows r0, r0+1

    float wmin = 0.f, wmax = 0.f, hmin = 0.f, hmax = 0.f;
    if (b >= 2) {
        const float* bb = bboxes + (b - 2) * 4;
        wmin = floorf(512.0f * bb[0]);
        hmin = floorf(512.0f * bb[1]);
        wmax = floorf(512.0f * bb[2]);
        hmax = floorf(512.0f * bb[3]);
        // block-level y test: rows r0..r0+1 -> taps [8*r0-4, 8*r0+19]
        float j0 = fmaxf(0.0f, 8.0f * r0 - 4.0f);
        float j1 = fminf(511.0f, 8.0f * r0 + 19.0f);
        if (fmaxf(j0, hmin) > fminf(j1, hmax - 1.0f)) return;  // w==0 everywhere
    }

    const float scale = 0.15811388300841897f;  // 1/sqrt(40)

    // cooperative loads (K/V padded to 80 rows with zeros)
    const float* Kb = K + (size_t)b * LKV * CC + h * DH;
    const float* Vb = V + (size_t)b * LKV * CC + h * DH;
    for (int idx = tid; idx < 80 * DH; idx += 256) {
        int r = idx / DH, c = idx - r * DH;
        float kv = 0.f, vv = 0.f;
        if (r < LKV) { kv = Kb[(size_t)r * CC + c]; vv = Vb[(size_t)r * CC + c]; }
        Ks[r * KST + c] = kv;
        Vs[r * VST + c] = vv;
    }
    int qb = (b == 0) ? 0 : 1;
    const float* Qb = Q + ((size_t)qb * HW + q0) * CC + h * DH;
    for (int idx = tid; idx < 128 * DH; idx += 256) {
        int r = idx / DH, c = idx - r * DH;
        S[r * QST + c] = Qb[(size_t)r * CC + c] * scale;
    }
    __syncthreads();

    // per-warp skip: warp covers image row wrow, cols [x0, x0+15]
    if (b >= 2) {
        int wrow = r0 + (wid >> 2);
        int x0 = (wid & 3) * 16;
        float jy0 = fmaxf(0.0f, 8.0f * wrow - 4.0f);
        float jy1 = fminf(511.0f, 8.0f * wrow + 11.0f);
        bool ok = fmaxf(jy0, hmin) <= fminf(jy1, hmax - 1.0f);
        float jx0 = fmaxf(0.0f, 8.0f * x0 - 4.0f);
        float jx1 = fminf(511.0f, 8.0f * (x0 + 15) + 11.0f);
        ok = ok && (fmaxf(jx0, wmin) <= fminf(jx1, wmax - 1.0f));
        if (!ok) return;                   // w==0 for all 16 rows of this warp
    }

    int rb = wid * 16;                     // warp's local row base

    // Q fragments (read before P overwrites the buffer)
    uint32_t a[5][4];
#pragma unroll
    for (int k5 = 0; k5 < 5; ++k5) {
        int kb = k5 * 8;
        a[k5][0] = __float_as_uint(S[(rb + g) * QST + kb + tg]);
        a[k5][1] = __float_as_uint(S[(rb + 8 + g) * QST + kb + tg]);
        a[k5][2] = __float_as_uint(S[(rb + g) * QST + kb + tg + 4]);
        a[k5][3] = __float_as_uint(S[(rb + 8 + g) * QST + kb + tg + 4]);
    }
    // tf32-round A in registers
#pragma unroll
    for (int k5 = 0; k5 < 5; ++k5)
#pragma unroll
        for (int f = 0; f < 4; ++f)
            a[k5][f] = __float_as_uint(tf32r(__uint_as_float(a[k5][f])));

    // QK^T: S16x80 = Q16x40 @ K80x40^T
    float c[10][4];
#pragma unroll
    for (int j = 0; j < 10; ++j)
#pragma unroll
        for (int f = 0; f < 4; ++f) c[j][f] = 0.0f;

#pragma unroll
    for (int k5 = 0; k5 < 5; ++k5) {
        int kb = k5 * 8;
#pragma unroll
        for (int j = 0; j < 10; ++j) {
            int nb = j * 8 + g;
            uint32_t bfr[2];
            bfr[0] = __float_as_uint(tf32r(Ks[nb * KST + kb + tg]));
            bfr[1] = __float_as_uint(tf32r(Ks[nb * KST + kb + tg + 4]));
            mma_tf32(c[j], a[k5], bfr);
        }
    }

    // softmax (no max-sub; logits ~O(1)); zero padded cols >= 77
    float l0 = 0.0f, l1 = 0.0f;
#pragma unroll
    for (int j = 0; j < 10; ++j) {
#pragma unroll
        for (int e = 0; e < 2; ++e) {
            int col = j * 8 + 2 * tg + e;
            float p0 = (col < LKV) ? __expf(c[j][e]) : 0.0f;
            float p1 = (col < LKV) ? __expf(c[j][2 + e]) : 0.0f;
            c[j][e] = p0; c[j][2 + e] = p1;
            l0 += p0; l1 += p1;
        }
    }
    l0 += __shfl_xor_sync(0xFFFFFFFF, l0, 1);
    l0 += __shfl_xor_sync(0xFFFFFFFF, l0, 2);
    l1 += __shfl_xor_sync(0xFFFFFFFF, l1, 1);
    l1 += __shfl_xor_sync(0xFFFFFFFF, l1, 2);

    // stage P into S (own rows only -> warp-local)
#pragma unroll
    for (int j = 0; j < 10; ++j) {
        *reinterpret_cast<float2*>(&S[(rb + g) * QST + j * 8 + 2 * tg]) =
            make_float2(c[j][0], c[j][1]);
        *reinterpret_cast<float2*>(&S[(rb + 8 + g) * QST + j * 8 + 2 * tg]) =
            make_float2(c[j][2], c[j][3]);
    }
    __syncwarp();

    // PV: O16x40 = P16x80 @ V80x40
    float o[5][4];
#pragma unroll
    for (int j2 = 0; j2 < 5; ++j2)
#pragma unroll
        for (int f = 0; f < 4; ++f) o[j2][f] = 0.0f;

#pragma unroll
    for (int k10 = 0; k10 < 10; ++k10) {
        int kb = k10 * 8;
        uint32_t pa[4];
        pa[0] = __float_as_uint(tf32r(S[(rb + g) * QST + kb + tg]));
        pa[1] = __float_as_uint(tf32r(S[(rb + 8 + g) * QST + kb + tg]));
        pa[2] = __float_as_uint(tf32r(S[(rb + g) * QST + kb + tg + 4]));
        pa[3] = __float_as_uint(tf32r(S[(rb + 8 + g) * QST + kb + tg + 4]));
#pragma unroll
        for (int j2 = 0; j2 < 5; ++j2) {
            int nb = j2 * 8 + g;
            uint32_t bfr[2];
            bfr[0] = __float_as_uint(tf32r(Vs[(kb + tg) * VST + nb]));
            bfr[1] = __float_as_uint(tf32r(Vs[(kb + tg + 4) * VST + nb]));
            mma_tf32(o[j2], pa, bfr);
        }
    }

    float inv0 = 1.0f / l0, inv1 = 1.0f / l1;
    float* base = (b == 0) ? final_in : (attn_out + (size_t)(b - 1) * HW * CC);
    int row0g = q0 + rb + g;
#pragma unroll
    for (int j2 = 0; j2 < 5; ++j2) {
        int col = h * DH + j2 * 8 + 2 * tg;
        *reinterpret_cast<float2*>(base + (size_t)row0g * CC + col) =
            make_float2(o[j2][0] * inv0, o[j2][1] * inv0);
        *reinterpret_cast<float2*>(base + (size_t)(row0g + 8) * CC + col) =
            make_float2(o[j2][2] * inv1, o[j2][3] * inv1);
    }
}

// ======================= weighted fusion (skip w==0 loads) ===================
__global__ __launch_bounds__(CC) void reduce_kernel(
    const float* __restrict__ attn, const float* __restrict__ pw,
    float* __restrict__ final_in, float* __restrict__ bscale)
{
    int pos = blockIdx.x;
    int c = threadIdx.x;
    __shared__ float w[9];
    __shared__ float sinv;
    if (c < 9) w[c] = pw[(size_t)c * HW + pos];
    __syncthreads();
    if (c == 0) {
        float s = 0.0f;
        for (int i = 0; i < 9; i++) s += w[i];
        float iv = 1.0f / (s + 1e-6f);
        sinv = iv;
        bscale[pos] = s * iv;
    }
    __syncthreads();
    float accv = 0.0f;
#pragma unroll
    for (int i = 0; i < 9; i++) {
        float wv = w[i];
        if (wv != 0.0f)                    // block-uniform branch; skips DRAM reads
            accv += wv * attn[((size_t)i * HW + pos) * CC + c];
    }
    final_in[((size_t)(HW + pos)) * CC + c] = accv * sinv;
}

// ======================= launch ==============================================
extern "C" void kernel_launch(void* const* d_in, const int* in_sizes, int n_in,
                              void* d_out, int out_size)
{
    const float* hidden = (const float*)d_in[0];   // (2, 4096, 320)
    const float* ehs    = (const float*)d_in[1];   // (11, 77, 768)
    const float* bbox   = (const float*)d_in[2];   // (1, 8, 4)
    const float* Wq     = (const float*)d_in[3];
    const float* Wk     = (const float*)d_in[4];
    const float* Wv     = (const float*)d_in[5];
    const float* Wo     = (const float*)d_in[6];
    const float* bo     = (const float*)d_in[7];
    float* out = (float*)d_out;

    float *Qp, *Kp, *Vp, *Ap, *Fp, *Pp, *Bp;
    cudaGetSymbolAddress((void**)&Qp, g_Q);
    cudaGetSymbolAddress((void**)&Kp, g_K);
    cudaGetSymbolAddress((void**)&Vp, g_V);
    cudaGetSymbolAddress((void**)&Ap, g_attn);
    cudaGetSymbolAddress((void**)&Fp, g_final);
    cudaGetSymbolAddress((void**)&Pp, g_pw);
    cudaGetSymbolAddress((void**)&Bp, g_bscale);

    cudaFuncSetAttribute(attn_kernel, cudaFuncAttributeMaxDynamicSharedMemorySize, ATTN_SMEM);

    // Q projection (tensor cores, tf32): 2 distinct hidden states only
    gemm_tf32<<<dim3(CC / 64, (2 * HW + 127) / 128), 256>>>(
        hidden, Wq, Qp, 2 * HW, CC, nullptr, nullptr, 0);

    // K / V projections on ehs[:-1] = first 770 rows
    gemm_tf32<<<dim3(CC / 64, (NBATCH * LKV + 127) / 128), 256>>>(
        ehs, Wk, Kp, NBATCH * LKV, CX, nullptr, nullptr, 0);
    gemm_tf32<<<dim3(CC / 64, (NBATCH * LKV + 127) / 128), 256>>>(
        ehs, Wv, Vp, NBATCH * LKV, CX, nullptr, nullptr, 0);

    // phase weights
    mask_kernel<<<(9 * HW + 127) / 128, 128>>>(bbox, Pp);

    // attention (tensor cores + mask-driven sparsity)
    attn_kernel<<<dim3(HW / 128, NHEAD, NBATCH), 256, ATTN_SMEM>>>(
        Qp, Kp, Vp, bbox, Ap, Fp);

    // weighted fusion (Wo deferred through linearity)
    reduce_kernel<<<HW, CC>>>(Ap, Pp, Fp, Bp);

    // output projection (tensor cores) + bias epilogue
    gemm_tf32<<<dim3(CC / 64, (2 * HW + 127) / 128), 256>>>(
        Fp, Wo, out, 2 * HW, CC, bo, Bp, 1);
}

// round 11
// speedup vs baseline: 3.3309x; 1.4931x over previous
#include <cuda_runtime.h>
#include <math.h>
#include <cstdint>

// Problem constants
#define HW    4096
#define CC    320
#define CX    768
#define LKV   77
#define DH    40
#define NHEAD 8
#define NBATCH 10
#define NINST 8

// ======================= scratch (allocation is banned) ======================
__device__ float g_Q[2 * HW * CC];
__device__ float g_K[NBATCH * LKV * CC];
__device__ float g_V[NBATCH * LKV * CC];
__device__ float g_attn[9 * HW * CC];
__device__ float g_final[2 * HW * CC];
__device__ float g_bscale[HW];
__device__ float g_hid_r[2 * HW * CC];
__device__ float g_ehs_r[NBATCH * LKV * CX];
__device__ float g_Wq_r[CC * CC];
__device__ float g_Wk_r[CX * CC];
__device__ float g_Wv_r[CX * CC];
__device__ float g_Wo_r[CC * CC];

// ======================= tf32 helpers ========================================
__device__ __forceinline__ float tf32r(float v) {
    uint32_t t;
    asm("cvt.rna.tf32.f32 %0, %1;" : "=r"(t) : "f"(v));
    return __uint_as_float(t);
}
__device__ __forceinline__ void mma_tf32(float c[4], const uint32_t a[4], const uint32_t b[2]) {
    asm volatile(
        "mma.sync.aligned.m16n8k8.row.col.f32.tf32.tf32.f32 "
        "{%0,%1,%2,%3}, {%4,%5,%6,%7}, {%8,%9}, {%0,%1,%2,%3};"
        : "+f"(c[0]), "+f"(c[1]), "+f"(c[2]), "+f"(c[3])
        : "r"(a[0]), "r"(a[1]), "r"(a[2]), "r"(a[3]), "r"(b[0]), "r"(b[1]));
}
__device__ __forceinline__ void cp16(uint32_t dst, const void* src, uint32_t sz) {
    asm volatile("cp.async.cg.shared.global [%0], [%1], 16, %2;"
                 :: "r"(dst), "l"(src), "r"(sz) : "memory");
}
#define CP_COMMIT() asm volatile("cp.async.commit_group;" ::: "memory")
#define CP_WAIT1()  asm volatile("cp.async.wait_group 1;" ::: "memory")
#define CP_WAIT0()  asm volatile("cp.async.wait_group 0;" ::: "memory")

// ======================= pre-round pass (fp32 -> tf32 rna) ===================
#define SEG0 (2 * HW * CC)
#define SEG1 (SEG0 + NBATCH * LKV * CX)
#define SEG2 (SEG1 + CC * CC)
#define SEG3 (SEG2 + CX * CC)
#define SEG4 (SEG3 + CX * CC)
#define SEG5 (SEG4 + CC * CC)

__global__ __launch_bounds__(256) void preround(
    const float* __restrict__ hid, const float* __restrict__ ehs,
    const float* __restrict__ Wq, const float* __restrict__ Wk,
    const float* __restrict__ Wv, const float* __restrict__ Wo,
    float* __restrict__ hid_r, float* __restrict__ ehs_r,
    float* __restrict__ wq_r, float* __restrict__ wk_r,
    float* __restrict__ wv_r, float* __restrict__ wo_r)
{
    const float scale = 0.15811388300841897f;  // 1/sqrt(40) folded into Wq
    int idx = blockIdx.x * 256 + threadIdx.x;
    if (idx < SEG0)       hid_r[idx]        = tf32r(hid[idx]);
    else if (idx < SEG1)  ehs_r[idx - SEG0] = tf32r(ehs[idx - SEG0]);
    else if (idx < SEG2)  wq_r[idx - SEG1]  = tf32r(Wq[idx - SEG1] * scale);
    else if (idx < SEG3)  wk_r[idx - SEG2]  = tf32r(Wk[idx - SEG2]);
    else if (idx < SEG4)  wv_r[idx - SEG3]  = tf32r(Wv[idx - SEG3]);
    else if (idx < SEG5)  wo_r[idx - SEG4]  = tf32r(Wo[idx - SEG4]);
}

// ======================= tf32 GEMM, cp.async double-buffered =================
// C[M x 320] = A[M x K] @ W[K x 320]; inputs pre-rounded to tf32.
// Block tile 128x64, 8 warps (4x2), warp tile 32x32, K chunks of 32, 2 stages.
// Optional second problem (W2/Cm2) for blockIdx.x >= nxblk (fused K/V).
#define AST 36
#define BST 72
#define STAGE_F (128 * AST + 32 * BST)
#define GSMEM (2 * STAGE_F * 4)

__global__ __launch_bounds__(256) void gemm_tf32(
    const float* __restrict__ A, const float* __restrict__ W, float* __restrict__ Cm,
    int M, int K,
    const float* __restrict__ W2, float* __restrict__ Cm2, int nxblk,
    const float* __restrict__ bias, const float* __restrict__ bscale, int mode)
{
    extern __shared__ float sm[];
    int bx = blockIdx.x;
    if (W2 != nullptr && bx >= nxblk) { W = W2; Cm = Cm2; bx -= nxblk; }

    int tid = threadIdx.x;
    int wid = tid >> 5, lane = tid & 31;
    int g = lane >> 2, tg = lane & 3;
    int wm = wid & 3, wn = wid >> 2;
    int m0 = blockIdx.y * 128, n0 = bx * 64;
    int NC = K / 32;

    uint32_t smb = (uint32_t)__cvta_generic_to_shared(sm);

    // per-thread load slots
    int ar = tid >> 1, ac = (tid & 1) * 16;       // A: 2 rows-of-128 per pass? no:
    // A tile: 1024 float4 slots; thread does 4 (idx = i*256+tid)
    // B tile: 512 float4 slots; thread does 2

    float c[2][4][4];
#pragma unroll
    for (int i = 0; i < 2; ++i)
#pragma unroll
        for (int j = 0; j < 4; ++j)
#pragma unroll
            for (int f = 0; f < 4; ++f) c[i][j][f] = 0.0f;

    (void)ar; (void)ac;

    // ---- async load of chunk k0 into stage buf ----
    auto load_stage = [&](int kc, int buf) {
        uint32_t base = smb + buf * STAGE_F * 4;
        int k0 = kc * 32;
#pragma unroll
        for (int i = 0; i < 4; ++i) {
            int idx = i * 256 + tid;
            int r = idx >> 3, c4 = idx & 7;
            int row = m0 + r;
            const float* src = A + (size_t)min(row, M - 1) * K + k0 + c4 * 4;
            cp16(base + (r * AST + c4 * 4) * 4, src, row < M ? 16u : 0u);
        }
#pragma unroll
        for (int i = 0; i < 2; ++i) {
            int idx = i * 256 + tid;
            int kr = idx >> 4, c4 = idx & 15;
            const float* src = W + (size_t)(k0 + kr) * CC + n0 + c4 * 4;
            cp16(base + (128 * AST + kr * BST + c4 * 4) * 4, src, 16u);
        }
        CP_COMMIT();
    };

    load_stage(0, 0);

    for (int kc = 0; kc < NC; ++kc) {
        int buf = kc & 1;
        if (kc + 1 < NC) { load_stage(kc + 1, (kc + 1) & 1); CP_WAIT1(); }
        else CP_WAIT0();
        __syncthreads();

        const float* As = sm + buf * STAGE_F;
        const float* Bs = As + 128 * AST;
#pragma unroll
        for (int k8 = 0; k8 < 4; ++k8) {
            int kb = k8 * 8;
            uint32_t a[2][4], b[4][2];
#pragma unroll
            for (int i = 0; i < 2; ++i) {
                int mb = (wm * 32 + i * 16 + g) * AST + kb + tg;
                a[i][0] = __float_as_uint(As[mb]);
                a[i][1] = __float_as_uint(As[mb + 8 * AST]);
                a[i][2] = __float_as_uint(As[mb + 4]);
                a[i][3] = __float_as_uint(As[mb + 8 * AST + 4]);
            }
#pragma unroll
            for (int j = 0; j < 4; ++j) {
                int nb = wn * 32 + j * 8 + g;
                b[j][0] = __float_as_uint(Bs[(kb + tg) * BST + nb]);
                b[j][1] = __float_as_uint(Bs[(kb + tg + 4) * BST + nb]);
            }
#pragma unroll
            for (int i = 0; i < 2; ++i)
#pragma unroll
                for (int j = 0; j < 4; ++j)
                    mma_tf32(c[i][j], a[i], b[j]);
        }
        __syncthreads();
    }

#pragma unroll
    for (int i = 0; i < 2; ++i) {
        int r0 = m0 + wm * 32 + i * 16 + g;
#pragma unroll
        for (int j = 0; j < 4; ++j) {
            int col = n0 + wn * 32 + j * 8 + 2 * tg;
#pragma unroll
            for (int h = 0; h < 2; ++h) {
                int row = r0 + h * 8;
                if (row >= M) continue;
                float v0 = c[i][j][h * 2 + 0];
                float v1 = c[i][j][h * 2 + 1];
                if (mode == 1) {
                    float bs = (row < HW) ? 1.0f : bscale[row - HW];
                    v0 += bias[col] * bs;
                    v1 += bias[col + 1] * bs;
                } else if (mode == 2) {
                    v0 = tf32r(v0);
                    v1 = tf32r(v1);
                }
                *reinterpret_cast<float2*>(Cm + (size_t)row * CC + col) = make_float2(v0, v1);
            }
        }
    }
}

// ======================= separable antialiased resize weight =================
__device__ __forceinline__ float axis_weight(int o, float lo, float hi)
{
    float c = 8.0f * o + 3.5f;
    int j0 = 8 * o - 4; if (j0 < 0) j0 = 0;
    int j1 = 8 * o + 11; if (j1 > 511) j1 = 511;
    float wsum = 0.0f, win = 0.0f;
    for (int j = j0; j <= j1; ++j) {
        float w = 1.0f - fabsf((float)j - c) * 0.125f;
        wsum += w;
        float jf = (float)j;
        if (jf >= lo && jf < hi) win += w;
    }
    return win / wsum;
}

// ======================= tensor-core attention with sparsity =================
// Inputs Q/K/V pre-rounded to tf32 (gemm mode=2); scale folded into Wq.
#define QST 84
#define KST 44
#define VST 40
#define ATTN_SMEM ((128 * QST + 80 * KST + 80 * VST) * 4)

__global__ __launch_bounds__(256) void attn_kernel(
    const float* __restrict__ Q, const float* __restrict__ K, const float* __restrict__ V,
    const float* __restrict__ bboxes,
    float* __restrict__ attn_out, float* __restrict__ final_in)
{
    extern __shared__ float sm[];
    float* S  = sm;                       // Q then P
    float* Ks = sm + 128 * QST;
    float* Vs = Ks + 80 * KST;

    int qt = blockIdx.x, h = blockIdx.y, b = blockIdx.z;
    int tid = threadIdx.x;
    int wid = tid >> 5, lane = tid & 31;
    int g = lane >> 2, tg = lane & 3;
    int q0 = qt * 128;
    int r0 = q0 >> 6;

    float wmin = 0.f, wmax = 0.f, hmin = 0.f, hmax = 0.f;
    if (b >= 2) {
        const float* bb = bboxes + (b - 2) * 4;
        wmin = floorf(512.0f * bb[0]);
        hmin = floorf(512.0f * bb[1]);
        wmax = floorf(512.0f * bb[2]);
        hmax = floorf(512.0f * bb[3]);
        float j0 = fmaxf(0.0f, 8.0f * r0 - 4.0f);
        float j1 = fminf(511.0f, 8.0f * r0 + 19.0f);
        if (fmaxf(j0, hmin) > fminf(j1, hmax - 1.0f)) return;
    }

    const float* Kb = K + (size_t)b * LKV * CC + h * DH;
    const float* Vb = V + (size_t)b * LKV * CC + h * DH;
    for (int idx = tid; idx < 80 * DH; idx += 256) {
        int r = idx / DH, c = idx - r * DH;
        float kv = 0.f, vv = 0.f;
        if (r < LKV) { kv = Kb[(size_t)r * CC + c]; vv = Vb[(size_t)r * CC + c]; }
        Ks[r * KST + c] = kv;
        Vs[r * VST + c] = vv;
    }
    int qb = (b == 0) ? 0 : 1;
    const float* Qb = Q + ((size_t)qb * HW + q0) * CC + h * DH;
    for (int idx = tid; idx < 128 * DH; idx += 256) {
        int r = idx / DH, c = idx - r * DH;
        S[r * QST + c] = Qb[(size_t)r * CC + c];
    }
    __syncthreads();

    if (b >= 2) {
        int wrow = r0 + (wid >> 2);
        int x0 = (wid & 3) * 16;
        float jy0 = fmaxf(0.0f, 8.0f * wrow - 4.0f);
        float jy1 = fminf(511.0f, 8.0f * wrow + 11.0f);
        bool ok = fmaxf(jy0, hmin) <= fminf(jy1, hmax - 1.0f);
        float jx0 = fmaxf(0.0f, 8.0f * x0 - 4.0f);
        float jx1 = fminf(511.0f, 8.0f * (x0 + 15) + 11.0f);
        ok = ok && (fmaxf(jx0, wmin) <= fminf(jx1, wmax - 1.0f));
        if (!ok) return;
    }

    int rb = wid * 16;

    uint32_t a[5][4];
#pragma unroll
    for (int k5 = 0; k5 < 5; ++k5) {
        int kb = k5 * 8;
        a[k5][0] = __float_as_uint(S[(rb + g) * QST + kb + tg]);
        a[k5][1] = __float_as_uint(S[(rb + 8 + g) * QST + kb + tg]);
        a[k5][2] = __float_as_uint(S[(rb + g) * QST + kb + tg + 4]);
        a[k5][3] = __float_as_uint(S[(rb + 8 + g) * QST + kb + tg + 4]);
    }

    float c[10][4];
#pragma unroll
    for (int j = 0; j < 10; ++j)
#pragma unroll
        for (int f = 0; f < 4; ++f) c[j][f] = 0.0f;

#pragma unroll
    for (int k5 = 0; k5 < 5; ++k5) {
        int kb = k5 * 8;
#pragma unroll
        for (int j = 0; j < 10; ++j) {
            int nb = j * 8 + g;
            uint32_t bfr[2];
            bfr[0] = __float_as_uint(Ks[nb * KST + kb + tg]);
            bfr[1] = __float_as_uint(Ks[nb * KST + kb + tg + 4]);
            mma_tf32(c[j], a[k5], bfr);
        }
    }

    // softmax (no max-sub; logits ~O(1)); zero padded cols >= 77
    float l0 = 0.0f, l1 = 0.0f;
#pragma unroll
    for (int j = 0; j < 10; ++j) {
#pragma unroll
        for (int e = 0; e < 2; ++e) {
            int col = j * 8 + 2 * tg + e;
            float p0 = (col < LKV) ? __expf(c[j][e]) : 0.0f;
            float p1 = (col < LKV) ? __expf(c[j][2 + e]) : 0.0f;
            p0 = tf32r(p0); p1 = tf32r(p1);
            c[j][e] = p0; c[j][2 + e] = p1;
            l0 += p0; l1 += p1;
        }
    }
    l0 += __shfl_xor_sync(0xFFFFFFFF, l0, 1);
    l0 += __shfl_xor_sync(0xFFFFFFFF, l0, 2);
    l1 += __shfl_xor_sync(0xFFFFFFFF, l1, 1);
    l1 += __shfl_xor_sync(0xFFFFFFFF, l1, 2);

#pragma unroll
    for (int j = 0; j < 10; ++j) {
        *reinterpret_cast<float2*>(&S[(rb + g) * QST + j * 8 + 2 * tg]) =
            make_float2(c[j][0], c[j][1]);
        *reinterpret_cast<float2*>(&S[(rb + 8 + g) * QST + j * 8 + 2 * tg]) =
            make_float2(c[j][2], c[j][3]);
    }
    __syncwarp();

    float o[5][4];
#pragma unroll
    for (int j2 = 0; j2 < 5; ++j2)
#pragma unroll
        for (int f = 0; f < 4; ++f) o[j2][f] = 0.0f;

#pragma unroll
    for (int k10 = 0; k10 < 10; ++k10) {
        int kb = k10 * 8;
        uint32_t pa[4];
        pa[0] = __float_as_uint(S[(rb + g) * QST + kb + tg]);
        pa[1] = __float_as_uint(S[(rb + 8 + g) * QST + kb + tg]);
        pa[2] = __float_as_uint(S[(rb + g) * QST + kb + tg + 4]);
        pa[3] = __float_as_uint(S[(rb + 8 + g) * QST + kb + tg + 4]);
#pragma unroll
        for (int j2 = 0; j2 < 5; ++j2) {
            int nb = j2 * 8 + g;
            uint32_t bfr[2];
            bfr[0] = __float_as_uint(Vs[(kb + tg) * VST + nb]);
            bfr[1] = __float_as_uint(Vs[(kb + tg + 4) * VST + nb]);
            mma_tf32(o[j2], pa, bfr);
        }
    }

    float inv0 = 1.0f / l0, inv1 = 1.0f / l1;
    int row0g = q0 + rb + g;
    if (b == 0) {
        // feeds the tf32 output GEMM -> store rounded
#pragma unroll
        for (int j2 = 0; j2 < 5; ++j2) {
            int col = h * DH + j2 * 8 + 2 * tg;
            *reinterpret_cast<float2*>(final_in + (size_t)row0g * CC + col) =
                make_float2(tf32r(o[j2][0] * inv0), tf32r(o[j2][1] * inv0));
            *reinterpret_cast<float2*>(final_in + (size_t)(row0g + 8) * CC + col) =
                make_float2(tf32r(o[j2][2] * inv1), tf32r(o[j2][3] * inv1));
        }
    } else {
        float* base = attn_out + (size_t)(b - 1) * HW * CC;
#pragma unroll
        for (int j2 = 0; j2 < 5; ++j2) {
            int col = h * DH + j2 * 8 + 2 * tg;
            *reinterpret_cast<float2*>(base + (size_t)row0g * CC + col) =
                make_float2(o[j2][0] * inv0, o[j2][1] * inv0);
            *reinterpret_cast<float2*>(base + (size_t)(row0g + 8) * CC + col) =
                make_float2(o[j2][2] * inv1, o[j2][3] * inv1);
        }
    }
}

// ======================= weighted fusion (mask inline) =======================
__global__ __launch_bounds__(CC) void reduce_kernel(
    const float* __restrict__ attn, const float* __restrict__ bboxes,
    float* __restrict__ final_in, float* __restrict__ bscale)
{
    int pos = blockIdx.x;
    int c = threadIdx.x;
    __shared__ float w[9];
    __shared__ float sinv;
    if (c == 0) {
        w[0] = 0.1f;
    } else if (c < 9) {
        int y = pos >> 6, x = pos & 63;
        const float* bb = bboxes + (c - 1) * 4;
        float wmin = floorf(512.0f * bb[0]);
        float hmin = floorf(512.0f * bb[1]);
        float wmax = floorf(512.0f * bb[2]);
        float hmax = floorf(512.0f * bb[3]);
        w[c] = axis_weight(y, hmin, hmax) * axis_weight(x, wmin, wmax) * 10.0f;
    }
    __syncthreads();
    if (c == 0) {
        float s = 0.0f;
        for (int i = 0; i < 9; i++) s += w[i];
        float iv = 1.0f / (s + 1e-6f);
        sinv = iv;
        bscale[pos] = s * iv;
    }
    __syncthreads();
    float accv = 0.0f;
#pragma unroll
    for (int i = 0; i < 9; i++) {
        float wv = w[i];
        if (wv != 0.0f)
            accv += wv * attn[((size_t)i * HW + pos) * CC + c];
    }
    final_in[((size_t)(HW + pos)) * CC + c] = tf32r(accv * sinv);
}

// ======================= launch ==============================================
extern "C" void kernel_launch(void* const* d_in, const int* in_sizes, int n_in,
                              void* d_out, int out_size)
{
    const float* hidden = (const float*)d_in[0];
    const float* ehs    = (const float*)d_in[1];
    const float* bbox   = (const float*)d_in[2];
    const float* Wq     = (const float*)d_in[3];
    const float* Wk     = (const float*)d_in[4];
    const float* Wv     = (const float*)d_in[5];
    const float* Wo     = (const float*)d_in[6];
    const float* bo     = (const float*)d_in[7];
    float* out = (float*)d_out;

    float *Qp, *Kp, *Vp, *Ap, *Fp, *Bp, *Hr, *Er, *Wqr, *Wkr, *Wvr, *Wor;
    cudaGetSymbolAddress((void**)&Qp, g_Q);
    cudaGetSymbolAddress((void**)&Kp, g_K);
    cudaGetSymbolAddress((void**)&Vp, g_V);
    cudaGetSymbolAddress((void**)&Ap, g_attn);
    cudaGetSymbolAddress((void**)&Fp, g_final);
    cudaGetSymbolAddress((void**)&Bp, g_bscale);
    cudaGetSymbolAddress((void**)&Hr, g_hid_r);
    cudaGetSymbolAddress((void**)&Er, g_ehs_r);
    cudaGetSymbolAddress((void**)&Wqr, g_Wq_r);
    cudaGetSymbolAddress((void**)&Wkr, g_Wk_r);
    cudaGetSymbolAddress((void**)&Wvr, g_Wv_r);
    cudaGetSymbolAddress((void**)&Wor, g_Wo_r);

    cudaFuncSetAttribute(gemm_tf32, cudaFuncAttributeMaxDynamicSharedMemorySize, GSMEM);
    cudaFuncSetAttribute(attn_kernel, cudaFuncAttributeMaxDynamicSharedMemorySize, ATTN_SMEM);

    // 1) round activations + weights to tf32 once (scale folded into Wq)
    preround<<<(SEG5 + 255) / 256, 256>>>(hidden, ehs, Wq, Wk, Wv, Wo,
                                          Hr, Er, Wqr, Wkr, Wvr, Wor);

    // 2) Q projection (pipelined tf32 MMA), tf32-rounded output
    gemm_tf32<<<dim3(5, 64), 256, GSMEM>>>(
        Hr, Wqr, Qp, 2 * HW, CC, nullptr, nullptr, 1 << 30, nullptr, nullptr, 2);

    // 3) fused K+V projection: blocks 0-4 -> K, 5-9 -> V
    gemm_tf32<<<dim3(10, 7), 256, GSMEM>>>(
        Er, Wkr, Kp, NBATCH * LKV, CX, Wvr, Vp, 5, nullptr, nullptr, 2);

    // 4) attention (tensor cores + box sparsity)
    attn_kernel<<<dim3(HW / 128, NHEAD, NBATCH), 256, ATTN_SMEM>>>(
        Qp, Kp, Vp, bbox, Ap, Fp);

    // 5) weighted fusion (mask computed inline; Wo deferred by linearity)
    reduce_kernel<<<HW, CC>>>(Ap, bbox, Fp, Bp);

    // 6) output projection + bias epilogue
    gemm_tf32<<<dim3(5, 64), 256, GSMEM>>>(
        Fp, Wor, out, 2 * HW, CC, nullptr, nullptr, 1 << 30, bo, Bp, 1);
}

// round 12
// speedup vs baseline: 3.7445x; 1.1242x over previous
#include <cuda_runtime.h>
#include <math.h>
#include <cstdint>

// Problem constants
#define HW    4096
#define CC    320
#define CX    768
#define LKV   77
#define DH    40
#define NHEAD 8
#define NBATCH 10
#define NINST 8

// ======================= scratch (allocation is banned) ======================
__device__ float g_Q[2 * HW * CC];
__device__ float g_K[NBATCH * LKV * CC];
__device__ float g_V[NBATCH * LKV * CC];
__device__ float g_attn[9 * HW * CC];
__device__ float g_final[2 * HW * CC];
__device__ float g_bscale[HW];
__device__ float g_hid_r[2 * HW * CC];
__device__ float g_ehs_r[NBATCH * LKV * CX];
__device__ float g_Wq_r[CC * CC];
__device__ float g_Wk_r[CX * CC];
__device__ float g_Wv_r[CX * CC];
__device__ float g_Wo_r[CC * CC];

// ======================= tf32 / mma helpers ==================================
__device__ __forceinline__ float tf32r(float v) {
    uint32_t t;
    asm("cvt.rna.tf32.f32 %0, %1;" : "=r"(t) : "f"(v));
    return __uint_as_float(t);
}
__device__ __forceinline__ void mma_tf32(float c[4], const uint32_t a[4], const uint32_t b[2]) {
    asm volatile(
        "mma.sync.aligned.m16n8k8.row.col.f32.tf32.tf32.f32 "
        "{%0,%1,%2,%3}, {%4,%5,%6,%7}, {%8,%9}, {%0,%1,%2,%3};"
        : "+f"(c[0]), "+f"(c[1]), "+f"(c[2]), "+f"(c[3])
        : "r"(a[0]), "r"(a[1]), "r"(a[2]), "r"(a[3]), "r"(b[0]), "r"(b[1]));
}
__device__ __forceinline__ void ldsm_x2(uint32_t& r0, uint32_t& r1, uint32_t addr) {
    asm volatile("ldmatrix.sync.aligned.m8n8.x2.shared.b16 {%0,%1}, [%2];"
                 : "=r"(r0), "=r"(r1) : "r"(addr));
}
__device__ __forceinline__ uint32_t smem_u32(const void* p) {
    return (uint32_t)__cvta_generic_to_shared(p);
}
__device__ __forceinline__ void cp16(uint32_t dst, const void* src, uint32_t sz) {
    asm volatile("cp.async.cg.shared.global [%0], [%1], 16, %2;"
                 :: "r"(dst), "l"(src), "r"(sz) : "memory");
}
#define CP_COMMIT() asm volatile("cp.async.commit_group;" ::: "memory")
#define CP_WAIT1()  asm volatile("cp.async.wait_group 1;" ::: "memory")
#define CP_WAIT0()  asm volatile("cp.async.wait_group 0;" ::: "memory")

// ======================= pre-round pass (fp32 -> tf32 rna) ===================
#define SEG0 (2 * HW * CC)
#define SEG1 (SEG0 + NBATCH * LKV * CX)
#define SEG2 (SEG1 + CC * CC)
#define SEG3 (SEG2 + CX * CC)
#define SEG4 (SEG3 + CX * CC)
#define SEG5 (SEG4 + CC * CC)

__global__ __launch_bounds__(256) void preround(
    const float* __restrict__ hid, const float* __restrict__ ehs,
    const float* __restrict__ Wq, const float* __restrict__ Wk,
    const float* __restrict__ Wv, const float* __restrict__ Wo,
    float* __restrict__ hid_r, float* __restrict__ ehs_r,
    float* __restrict__ wq_r, float* __restrict__ wk_r,
    float* __restrict__ wv_r, float* __restrict__ wo_r)
{
    const float scale = 0.15811388300841897f;  // 1/sqrt(40) folded into Wq
    int idx = blockIdx.x * 256 + threadIdx.x;
    if (idx < SEG0)       hid_r[idx]        = tf32r(hid[idx]);
    else if (idx < SEG1)  ehs_r[idx - SEG0] = tf32r(ehs[idx - SEG0]);
    else if (idx < SEG2)  wq_r[idx - SEG1]  = tf32r(Wq[idx - SEG1] * scale);
    else if (idx < SEG3)  wk_r[idx - SEG2]  = tf32r(Wk[idx - SEG2]);
    else if (idx < SEG4)  wv_r[idx - SEG3]  = tf32r(Wv[idx - SEG3]);
    else if (idx < SEG5)  wo_r[idx - SEG4]  = tf32r(Wo[idx - SEG4]);
}

// ======================= tf32 GEMM, cp.async double-buffered (R11-proven) ====
#define AST 36
#define BST 72
#define STAGE_F (128 * AST + 32 * BST)
#define GSMEM (2 * STAGE_F * 4)

__global__ __launch_bounds__(256) void gemm_tf32(
    const float* __restrict__ A, const float* __restrict__ W, float* __restrict__ Cm,
    int M, int K,
    const float* __restrict__ W2, float* __restrict__ Cm2, int nxblk,
    const float* __restrict__ bias, const float* __restrict__ bscale, int mode)
{
    extern __shared__ float sm[];
    int bx = blockIdx.x;
    if (W2 != nullptr && bx >= nxblk) { W = W2; Cm = Cm2; bx -= nxblk; }

    int tid = threadIdx.x;
    int wid = tid >> 5, lane = tid & 31;
    int g = lane >> 2, tg = lane & 3;
    int wm = wid & 3, wn = wid >> 2;
    int m0 = blockIdx.y * 128, n0 = bx * 64;
    int NC = K / 32;

    uint32_t smb = smem_u32(sm);

    float c[2][4][4];
#pragma unroll
    for (int i = 0; i < 2; ++i)
#pragma unroll
        for (int j = 0; j < 4; ++j)
#pragma unroll
            for (int f = 0; f < 4; ++f) c[i][j][f] = 0.0f;

    auto load_stage = [&](int kc, int buf) {
        uint32_t base = smb + buf * STAGE_F * 4;
        int k0 = kc * 32;
#pragma unroll
        for (int i = 0; i < 4; ++i) {
            int idx = i * 256 + tid;
            int r = idx >> 3, c4 = idx & 7;
            int row = m0 + r;
            const float* src = A + (size_t)min(row, M - 1) * K + k0 + c4 * 4;
            cp16(base + (r * AST + c4 * 4) * 4, src, row < M ? 16u : 0u);
        }
#pragma unroll
        for (int i = 0; i < 2; ++i) {
            int idx = i * 256 + tid;
            int kr = idx >> 4, c4 = idx & 15;
            const float* src = W + (size_t)(k0 + kr) * CC + n0 + c4 * 4;
            cp16(base + (128 * AST + kr * BST + c4 * 4) * 4, src, 16u);
        }
        CP_COMMIT();
    };

    load_stage(0, 0);

    for (int kc = 0; kc < NC; ++kc) {
        int buf = kc & 1;
        if (kc + 1 < NC) { load_stage(kc + 1, (kc + 1) & 1); CP_WAIT1(); }
        else CP_WAIT0();
        __syncthreads();

        const float* As = sm + buf * STAGE_F;
        const float* Bs = As + 128 * AST;
#pragma unroll
        for (int k8 = 0; k8 < 4; ++k8) {
            int kb = k8 * 8;
            uint32_t a[2][4], b[4][2];
#pragma unroll
            for (int i = 0; i < 2; ++i) {
                int mb = (wm * 32 + i * 16 + g) * AST + kb + tg;
                a[i][0] = __float_as_uint(As[mb]);
                a[i][1] = __float_as_uint(As[mb + 8 * AST]);
                a[i][2] = __float_as_uint(As[mb + 4]);
                a[i][3] = __float_as_uint(As[mb + 8 * AST + 4]);
            }
#pragma unroll
            for (int j = 0; j < 4; ++j) {
                int nb = wn * 32 + j * 8 + g;
                b[j][0] = __float_as_uint(Bs[(kb + tg) * BST + nb]);
                b[j][1] = __float_as_uint(Bs[(kb + tg + 4) * BST + nb]);
            }
#pragma unroll
            for (int i = 0; i < 2; ++i)
#pragma unroll
                for (int j = 0; j < 4; ++j)
                    mma_tf32(c[i][j], a[i], b[j]);
        }
        __syncthreads();
    }

#pragma unroll
    for (int i = 0; i < 2; ++i) {
        int r0 = m0 + wm * 32 + i * 16 + g;
#pragma unroll
        for (int j = 0; j < 4; ++j) {
            int col = n0 + wn * 32 + j * 8 + 2 * tg;
#pragma unroll
            for (int h = 0; h < 2; ++h) {
                int row = r0 + h * 8;
                if (row >= M) continue;
                float v0 = c[i][j][h * 2 + 0];
                float v1 = c[i][j][h * 2 + 1];
                if (mode == 1) {
                    float bs = (row < HW) ? 1.0f : bscale[row - HW];
                    v0 += bias[col] * bs;
                    v1 += bias[col + 1] * bs;
                } else if (mode == 2) {
                    v0 = tf32r(v0);
                    v1 = tf32r(v1);
                }
                *reinterpret_cast<float2*>(Cm + (size_t)row * CC + col) = make_float2(v0, v1);
            }
        }
    }
}

// ======================= separable antialiased resize weight =================
__device__ __forceinline__ float axis_weight(int o, float lo, float hi)
{
    float c = 8.0f * o + 3.5f;
    int j0 = 8 * o - 4; if (j0 < 0) j0 = 0;
    int j1 = 8 * o + 11; if (j1 > 511) j1 = 511;
    float wsum = 0.0f, win = 0.0f;
    for (int j = j0; j <= j1; ++j) {
        float w = 1.0f - fabsf((float)j - c) * 0.125f;
        wsum += w;
        float jf = (float)j;
        if (jf >= lo && jf < hi) win += w;
    }
    return win / wsum;
}

// ======================= attention: ldmatrix + shuffle-transpose =============
// smem: Ks[80][KST] (K, [n][k]) + Vt[40][VTST] (V transposed, [n][k]).
// Q fragments straight from gmem (tf32 pre-rounded). No Q/P staging buffer.
#define KST  44
#define VTST 84
#define ATTN_SMEM ((80 * KST + 40 * VTST) * 4)

__global__ __launch_bounds__(256) void attn_kernel(
    const float* __restrict__ Q, const float* __restrict__ K, const float* __restrict__ V,
    const float* __restrict__ bboxes,
    float* __restrict__ attn_out, float* __restrict__ final_in)
{
    extern __shared__ float sm[];
    float* Ks = sm;                 // [80][KST]
    float* Vt = sm + 80 * KST;      // [40][VTST]

    int qt = blockIdx.x, h = blockIdx.y, b = blockIdx.z;
    int tid = threadIdx.x;
    int wid = tid >> 5, lane = tid & 31;
    int g = lane >> 2, tg = lane & 3;
    int q0 = qt * 128;
    int r0 = q0 >> 6;

    float wmin = 0.f, wmax = 0.f, hmin = 0.f, hmax = 0.f;
    if (b >= 2) {
        const float* bb = bboxes + (b - 2) * 4;
        wmin = floorf(512.0f * bb[0]);
        hmin = floorf(512.0f * bb[1]);
        wmax = floorf(512.0f * bb[2]);
        hmax = floorf(512.0f * bb[3]);
        float j0 = fmaxf(0.0f, 8.0f * r0 - 4.0f);
        float j1 = fminf(511.0f, 8.0f * r0 + 19.0f);
        if (fmaxf(j0, hmin) > fminf(j1, hmax - 1.0f)) return;
    }

    // cooperative K/V load; V stored transposed. rows 77..79 zero-padded.
    const float* Kb = K + (size_t)b * LKV * CC + h * DH;
    const float* Vb = V + (size_t)b * LKV * CC + h * DH;
    for (int idx = tid; idx < 80 * DH; idx += 256) {
        int r = idx / DH, c = idx - r * DH;
        float kv = 0.f, vv = 0.f;
        if (r < LKV) { kv = Kb[(size_t)r * CC + c]; vv = Vb[(size_t)r * CC + c]; }
        Ks[r * KST + c] = kv;
        Vt[c * VTST + r] = vv;
    }
    __syncthreads();

    // per-warp sparsity skip (after the cooperative load + barrier)
    if (b >= 2) {
        int wrow = r0 + (wid >> 2);
        int x0 = (wid & 3) * 16;
        float jy0 = fmaxf(0.0f, 8.0f * wrow - 4.0f);
        float jy1 = fminf(511.0f, 8.0f * wrow + 11.0f);
        bool ok = fmaxf(jy0, hmin) <= fminf(jy1, hmax - 1.0f);
        float jx0 = fmaxf(0.0f, 8.0f * x0 - 4.0f);
        float jx1 = fminf(511.0f, 8.0f * (x0 + 15) + 11.0f);
        ok = ok && (fmaxf(jx0, wmin) <= fminf(jx1, wmax - 1.0f));
        if (!ok) return;
    }

    int rb = wid * 16;
    int qb = (b == 0) ? 0 : 1;
    const float* Qg = Q + ((size_t)qb * HW + q0 + rb) * CC + h * DH;

    // ldmatrix lane base: lanes 0-7 -> matrix0 rows (col +0); 8-15 -> matrix1 (col +4)
    uint32_t kbase = smem_u32(Ks) + (((lane & 7) * KST + ((lane >> 3) & 1) * 4) * 4);
    uint32_t vbase = smem_u32(Vt) + (((lane & 7) * VTST + ((lane >> 3) & 1) * 4) * 4);

    // ---------------- QK^T: S16x80 ----------------
    float c[10][4];
#pragma unroll
    for (int j = 0; j < 10; ++j)
#pragma unroll
        for (int f = 0; f < 4; ++f) c[j][f] = 0.0f;

#pragma unroll
    for (int k5 = 0; k5 < 5; ++k5) {
        int kb = k5 * 8;
        uint32_t a[4];
        a[0] = __float_as_uint(Qg[(size_t)g * CC + kb + tg]);
        a[1] = __float_as_uint(Qg[(size_t)(g + 8) * CC + kb + tg]);
        a[2] = __float_as_uint(Qg[(size_t)g * CC + kb + tg + 4]);
        a[3] = __float_as_uint(Qg[(size_t)(g + 8) * CC + kb + tg + 4]);
#pragma unroll
        for (int j = 0; j < 10; ++j) {
            uint32_t bfr[2];
            ldsm_x2(bfr[0], bfr[1], kbase + (j * 8 * KST + kb) * 4);
            mma_tf32(c[j], a, bfr);
        }
    }

    // ---------------- softmax (no max-sub; logits ~O(1)) ----------------
    float l0 = 0.0f, l1 = 0.0f;
#pragma unroll
    for (int j = 0; j < 10; ++j) {
#pragma unroll
        for (int e = 0; e < 2; ++e) {
            int col = j * 8 + 2 * tg + e;
            float p0 = (col < LKV) ? __expf(c[j][e]) : 0.0f;
            float p1 = (col < LKV) ? __expf(c[j][2 + e]) : 0.0f;
            p0 = tf32r(p0); p1 = tf32r(p1);
            c[j][e] = p0; c[j][2 + e] = p1;
            l0 += p0; l1 += p1;
        }
    }
    l0 += __shfl_xor_sync(0xFFFFFFFF, l0, 1);
    l0 += __shfl_xor_sync(0xFFFFFFFF, l0, 2);
    l1 += __shfl_xor_sync(0xFFFFFFFF, l1, 1);
    l1 += __shfl_xor_sync(0xFFFFFFFF, l1, 2);

    // ---------------- PV: O16x40, P via shuffle-transpose ----------------
    // C-frag (row, col 2tg+e) -> A-frag (row, col tg / tg+4): intra-quad shfl.
    float o[5][4];
#pragma unroll
    for (int j2 = 0; j2 < 5; ++j2)
#pragma unroll
        for (int f = 0; f < 4; ++f) o[j2][f] = 0.0f;

    int s0 = (lane & ~3) | (tg >> 1);
    int s1 = s0 + 2;
    bool oddc = (tg & 1);

#pragma unroll
    for (int k10 = 0; k10 < 10; ++k10) {
        float x0 = __shfl_sync(0xFFFFFFFF, c[k10][0], s0);
        float x1 = __shfl_sync(0xFFFFFFFF, c[k10][1], s0);
        float y0 = __shfl_sync(0xFFFFFFFF, c[k10][0], s1);
        float y1 = __shfl_sync(0xFFFFFFFF, c[k10][1], s1);
        float z0 = __shfl_sync(0xFFFFFFFF, c[k10][2], s0);
        float z1 = __shfl_sync(0xFFFFFFFF, c[k10][3], s0);
        float u0 = __shfl_sync(0xFFFFFFFF, c[k10][2], s1);
        float u1 = __shfl_sync(0xFFFFFFFF, c[k10][3], s1);
        uint32_t pa[4];
        pa[0] = __float_as_uint(oddc ? x1 : x0);   // (g,    tg)
        pa[1] = __float_as_uint(oddc ? z1 : z0);   // (g+8,  tg)
        pa[2] = __float_as_uint(oddc ? y1 : y0);   // (g,    tg+4)
        pa[3] = __float_as_uint(oddc ? u1 : u0);   // (g+8,  tg+4)
#pragma unroll
        for (int j2 = 0; j2 < 5; ++j2) {
            uint32_t bfr[2];
            ldsm_x2(bfr[0], bfr[1], vbase + (j2 * 8 * VTST + k10 * 8) * 4);
            mma_tf32(o[j2], pa, bfr);
        }
    }

    float inv0 = 1.0f / l0, inv1 = 1.0f / l1;
    int row0g = q0 + rb + g;
    if (b == 0) {
#pragma unroll
        for (int j2 = 0; j2 < 5; ++j2) {
            int col = h * DH + j2 * 8 + 2 * tg;
            *reinterpret_cast<float2*>(final_in + (size_t)row0g * CC + col) =
                make_float2(tf32r(o[j2][0] * inv0), tf32r(o[j2][1] * inv0));
            *reinterpret_cast<float2*>(final_in + (size_t)(row0g + 8) * CC + col) =
                make_float2(tf32r(o[j2][2] * inv1), tf32r(o[j2][3] * inv1));
        }
    } else {
        float* base = attn_out + (size_t)(b - 1) * HW * CC;
#pragma unroll
        for (int j2 = 0; j2 < 5; ++j2) {
            int col = h * DH + j2 * 8 + 2 * tg;
            *reinterpret_cast<float2*>(base + (size_t)row0g * CC + col) =
                make_float2(o[j2][0] * inv0, o[j2][1] * inv0);
            *reinterpret_cast<float2*>(base + (size_t)(row0g + 8) * CC + col) =
                make_float2(o[j2][2] * inv1, o[j2][3] * inv1);
        }
    }
}

// ======================= weighted fusion (mask inline) =======================
__global__ __launch_bounds__(CC) void reduce_kernel(
    const float* __restrict__ attn, const float* __restrict__ bboxes,
    float* __restrict__ final_in, float* __restrict__ bscale)
{
    int pos = blockIdx.x;
    int c = threadIdx.x;
    __shared__ float w[9];
    __shared__ float sinv;
    if (c == 0) {
        w[0] = 0.1f;
    } else if (c < 9) {
        int y = pos >> 6, x = pos & 63;
        const float* bb = bboxes + (c - 1) * 4;
        float wmin = floorf(512.0f * bb[0]);
        float hmin = floorf(512.0f * bb[1]);
        float wmax = floorf(512.0f * bb[2]);
        float hmax = floorf(512.0f * bb[3]);
        w[c] = axis_weight(y, hmin, hmax) * axis_weight(x, wmin, wmax) * 10.0f;
    }
    __syncthreads();
    if (c == 0) {
        float s = 0.0f;
        for (int i = 0; i < 9; i++) s += w[i];
        float iv = 1.0f / (s + 1e-6f);
        sinv = iv;
        bscale[pos] = s * iv;
    }
    __syncthreads();
    float accv = 0.0f;
#pragma unroll
    for (int i = 0; i < 9; i++) {
        float wv = w[i];
        if (wv != 0.0f)
            accv += wv * attn[((size_t)i * HW + pos) * CC + c];
    }
    final_in[((size_t)(HW + pos)) * CC + c] = tf32r(accv * sinv);
}

// ======================= launch ==============================================
extern "C" void kernel_launch(void* const* d_in, const int* in_sizes, int n_in,
                              void* d_out, int out_size)
{
    const float* hidden = (const float*)d_in[0];
    const float* ehs    = (const float*)d_in[1];
    const float* bbox   = (const float*)d_in[2];
    const float* Wq     = (const float*)d_in[3];
    const float* Wk     = (const float*)d_in[4];
    const float* Wv     = (const float*)d_in[5];
    const float* Wo     = (const float*)d_in[6];
    const float* bo     = (const float*)d_in[7];
    float* out = (float*)d_out;

    float *Qp, *Kp, *Vp, *Ap, *Fp, *Bp, *Hr, *Er, *Wqr, *Wkr, *Wvr, *Wor;
    cudaGetSymbolAddress((void**)&Qp, g_Q);
    cudaGetSymbolAddress((void**)&Kp, g_K);
    cudaGetSymbolAddress((void**)&Vp, g_V);
    cudaGetSymbolAddress((void**)&Ap, g_attn);
    cudaGetSymbolAddress((void**)&Fp, g_final);
    cudaGetSymbolAddress((void**)&Bp, g_bscale);
    cudaGetSymbolAddress((void**)&Hr, g_hid_r);
    cudaGetSymbolAddress((void**)&Er, g_ehs_r);
    cudaGetSymbolAddress((void**)&Wqr, g_Wq_r);
    cudaGetSymbolAddress((void**)&Wkr, g_Wk_r);
    cudaGetSymbolAddress((void**)&Wvr, g_Wv_r);
    cudaGetSymbolAddress((void**)&Wor, g_Wo_r);

    cudaFuncSetAttribute(gemm_tf32, cudaFuncAttributeMaxDynamicSharedMemorySize, GSMEM);
    cudaFuncSetAttribute(attn_kernel, cudaFuncAttributeMaxDynamicSharedMemorySize, ATTN_SMEM);

    // 1) round activations + weights to tf32 once (scale folded into Wq)
    preround<<<(SEG5 + 255) / 256, 256>>>(hidden, ehs, Wq, Wk, Wv, Wo,
                                          Hr, Er, Wqr, Wkr, Wvr, Wor);

    // 2) Q projection (pipelined tf32 MMA), tf32-rounded output
    gemm_tf32<<<dim3(5, 64), 256, GSMEM>>>(
        Hr, Wqr, Qp, 2 * HW, CC, nullptr, nullptr, 1 << 30, nullptr, nullptr, 2);

    // 3) fused K+V projection: blocks 0-4 -> K, 5-9 -> V
    gemm_tf32<<<dim3(10, 7), 256, GSMEM>>>(
        Er, Wkr, Kp, NBATCH * LKV, CX, Wvr, Vp, 5, nullptr, nullptr, 2);

    // 4) attention (ldmatrix + shuffle-transpose + box sparsity)
    attn_kernel<<<dim3(HW / 128, NHEAD, NBATCH), 256, ATTN_SMEM>>>(
        Qp, Kp, Vp, bbox, Ap, Fp);

    // 5) weighted fusion (mask inline; Wo deferred by linearity)
    reduce_kernel<<<HW, CC>>>(Ap, bbox, Fp, Bp);

    // 6) output projection + bias epilogue
    gemm_tf32<<<dim3(5, 64), 256, GSMEM>>>(
        Fp, Wor, out, 2 * HW, CC, nullptr, nullptr, 1 << 30, bo, Bp, 1);
}